// round 9
// baseline (speedup 1.0000x reference)
#include <cuda_runtime.h>
#include <cuda_bf16.h>

#define BB 8
#define NN 16384
#define DD 512
#define MV 8
#define NBA 64                      // pass-A blocks per batch (256 rows each)
#define NBB 128                     // pass-B blocks per batch (128 rows each)
#define SCALE_F 0.1f
#define EPS_F 1e-5f

__device__ float g_partial[BB][NBA][DD];       // 1 MB  column partial sums
__device__ float g_P[BB][NN][MV];              // 4 MB  particle multivectors
__device__ float g_F[BB][DD];                  // SCALE*(bo + sum_i bp_i*W2_i)... bp NOT folded (P has bp)
__device__ __nv_bfloat16 g_SW2h[BB][MV * DD];  // SCALE*Cayley-folded Wo, bf16

__device__ __forceinline__ void stcs(float4* p, float4 v) {
    asm volatile("st.global.cs.v4.f32 [%0], {%1,%2,%3,%4};"
                 :: "l"(p), "f"(v.x), "f"(v.y), "f"(v.z), "f"(v.w));
}

// ---------------------------------------------------------------------------
// Pass A: stream x once -> P dots (bf16 Wp) + column sums.
// grid (NBA, BB), 256 threads (8 warps). Warp: 32 rows, 2/iter, prefetch.
// ---------------------------------------------------------------------------
__global__ void __launch_bounds__(256, 3)
k_dots(const float* __restrict__ x, const float* __restrict__ Wp,
       const float* __restrict__ bp) {
    __shared__ __nv_bfloat16 Wp_s[MV * DD];   // 8 KB
    __shared__ float bp_s[MV];
    __shared__ float4 col_s[8][DD / 4];       // 16 KB

    int b = blockIdx.y, t = threadIdx.x;
    for (int i = t; i < MV * DD; i += 256) Wp_s[i] = __float2bfloat16(Wp[i]);
    if (t < MV) bp_s[t] = bp[t];
    __syncthreads();

    int w = t >> 5, l = t & 31;
    int g = l & 7;
    size_t rowbase = (size_t)blockIdx.x * 256 + (size_t)w * 32;
    const float4* xp = (const float4*)(x + ((size_t)b * NN + rowbase) * DD);

    float4 acc[4];
#pragma unroll
    for (int c = 0; c < 4; ++c) acc[c] = make_float4(0.f, 0.f, 0.f, 0.f);

    // prologue
    float4 v0[4], v1[4];
#pragma unroll
    for (int c = 0; c < 4; ++c) {
        v0[c] = xp[c * 32 + l];
        v1[c] = xp[128 + c * 32 + l];
    }

    for (int it = 0; it < 16; ++it) {
        float4 n0[4], n1[4];
        if (it < 15) {
#pragma unroll
            for (int c = 0; c < 4; ++c) {
                n0[c] = xp[(size_t)(it * 2 + 2) * 128 + c * 32 + l];
                n1[c] = xp[(size_t)(it * 2 + 3) * 128 + c * 32 + l];
            }
        }

        // column sums
#pragma unroll
        for (int c = 0; c < 4; ++c) {
            acc[c].x += v0[c].x + v1[c].x; acc[c].y += v0[c].y + v1[c].y;
            acc[c].z += v0[c].z + v1[c].z; acc[c].w += v0[c].w + v1[c].w;
        }

        // 8 per-lane partial dots per row (bf16 weights)
        float p0[8], p1[8];
#pragma unroll
        for (int i = 0; i < MV; ++i) {
            float s0 = 0.f, s1 = 0.f;
#pragma unroll
            for (int c = 0; c < 4; ++c) {
                uint2 u = *(const uint2*)&Wp_s[i * DD + c * 128 + l * 4];
                float2 a01 = __bfloat1622float2(*(const __nv_bfloat162*)&u.x);
                float2 a23 = __bfloat1622float2(*(const __nv_bfloat162*)&u.y);
                s0 += v0[c].x * a01.x + v0[c].y * a01.y + v0[c].z * a23.x + v0[c].w * a23.y;
                s1 += v1[c].x * a01.x + v1[c].y * a01.y + v1[c].z * a23.x + v1[c].w * a23.y;
            }
            p0[i] = s0; p1[i] = s1;
        }
        // group reduce (1,2,4), select component g, cross-group (8,16)
#pragma unroll
        for (int o = 1; o <= 4; o <<= 1) {
#pragma unroll
            for (int i = 0; i < MV; ++i) {
                p0[i] += __shfl_xor_sync(0xffffffffu, p0[i], o);
                p1[i] += __shfl_xor_sync(0xffffffffu, p1[i], o);
            }
        }
        float vd0 = p0[0], vd1 = p1[0];
#pragma unroll
        for (int i = 1; i < MV; ++i) { if (g == i) { vd0 = p0[i]; vd1 = p1[i]; } }
        vd0 += __shfl_xor_sync(0xffffffffu, vd0, 8);
        vd0 += __shfl_xor_sync(0xffffffffu, vd0, 16);
        vd1 += __shfl_xor_sync(0xffffffffu, vd1, 8);
        vd1 += __shfl_xor_sync(0xffffffffu, vd1, 16);

        if (l < 16) {
            float out = ((l < 8) ? vd0 : vd1) + bp_s[g];
            g_P[b][rowbase + it * 2 + (l >> 3)][g] = out;
        }

        if (it < 15) {
#pragma unroll
            for (int c = 0; c < 4; ++c) { v0[c] = n0[c]; v1[c] = n1[c]; }
        }
    }

    // block-level column reduction
#pragma unroll
    for (int c = 0; c < 4; ++c) col_s[w][c * 32 + l] = acc[c];
    __syncthreads();
    if (t < 128) {
        float4 s = col_s[0][t];
#pragma unroll
        for (int ww = 1; ww < 8; ++ww) {
            float4 a = col_s[ww][t];
            s.x += a.x; s.y += a.y; s.z += a.z; s.w += a.w;
        }
        ((float4*)&g_partial[b][blockIdx.x][0])[t] = s;
    }
}

// ---------------------------------------------------------------------------
// Pass 2: per-batch prep. mean -> mf -> Cayley fold -> SW2(bf16), F = SCALE*bo
// (bp is already inside P, so F has no bp term)
// ---------------------------------------------------------------------------
__global__ void k_prep(const float* __restrict__ Wm, const float* __restrict__ bm,
                       const float* __restrict__ Wo, const float* __restrict__ bo) {
    __shared__ float mean_s[DD];
    __shared__ float mf_s[MV];
    __shared__ float M_s[MV][MV];
    int b = blockIdx.x, t = threadIdx.x;  // 512 threads

    float acc = 0.f;
    for (int s = 0; s < NBA; ++s) acc += g_partial[b][s][t];
    mean_s[t] = acc * (1.0f / NN);
    __syncthreads();

    int w = t >> 5, l = t & 31;
    if (w < MV) {
        float p = 0.f;
#pragma unroll
        for (int c = 0; c < 16; ++c) p += mean_s[l + 32 * c] * Wm[w * DD + l + 32 * c];
#pragma unroll
        for (int o = 16; o; o >>= 1) p += __shfl_xor_sync(0xffffffffu, p, o);
        if (l == 0) mf_s[w] = p + bm[w];
    }
    __syncthreads();

    if (t < 64) {
        const int maskT[8] = {0, 1, 2, 4, 3, 5, 6, 7};
        const int idxT[8]  = {0, 1, 2, 4, 3, 5, 6, 7};
        int i = t >> 3, j = t & 7;
        int a = maskT[i], bj = maskT[j];
        int sgn = 0, aa = a >> 1;
        while (aa) { sgn += __popc(aa & bj); aa >>= 1; }
        int k = idxT[a ^ bj];
        M_s[i][k] = ((sgn & 1) ? -1.f : 1.f) * mf_s[j];
    }
    __syncthreads();

    float wo[8];
#pragma unroll
    for (int k = 0; k < 8; ++k) wo[k] = Wo[t * 8 + k];
#pragma unroll
    for (int i = 0; i < MV; ++i) {
        float w2 = 0.f;
#pragma unroll
        for (int k = 0; k < 8; ++k) w2 += M_s[i][k] * wo[k];
        g_SW2h[b][i * DD + t] = __float2bfloat16(SCALE_F * w2);
    }
    g_F[b][t] = SCALE_F * bo[t];
}

// ---------------------------------------------------------------------------
// Pass B: streaming y = LN(x + F + P @ SW2). grid (NBB, BB), 256 threads.
// Warp: 16 rows, 2/iter, prefetch. No dots, no broadcast — P via __ldg.
// ---------------------------------------------------------------------------
__global__ void __launch_bounds__(256, 3)
k_out(const float* __restrict__ x, const float* __restrict__ gamma,
      const float* __restrict__ beta, float* __restrict__ y) {
    __shared__ __nv_bfloat16 SW2_s[MV * DD];   // 8 KB
    __shared__ float F_s[DD], gm_s[DD], bt_s[DD];

    int b = blockIdx.y, t = threadIdx.x;
    const __nv_bfloat16* sw2g = &g_SW2h[b][0];
    for (int i = t; i < MV * DD; i += 256) SW2_s[i] = sw2g[i];
    for (int i = t; i < DD; i += 256) { F_s[i] = g_F[b][i]; gm_s[i] = gamma[i]; bt_s[i] = beta[i]; }
    __syncthreads();

    int w = t >> 5, l = t & 31;
    size_t rowbase = (size_t)blockIdx.x * 128 + (size_t)w * 16;
    const float4* xp = (const float4*)(x + ((size_t)b * NN + rowbase) * DD);
    float4* yp = (float4*)(y + ((size_t)b * NN + rowbase) * DD);
    const float4* Pp = (const float4*)&g_P[b][rowbase][0];

    // prologue
    float4 v0[4], v1[4];
#pragma unroll
    for (int c = 0; c < 4; ++c) {
        v0[c] = xp[c * 32 + l];
        v1[c] = xp[128 + c * 32 + l];
    }

    for (int it = 0; it < 8; ++it) {
        float4 n0[4], n1[4];
        if (it < 7) {
#pragma unroll
            for (int c = 0; c < 4; ++c) {
                n0[c] = xp[(size_t)(it * 2 + 2) * 128 + c * 32 + l];
                n1[c] = xp[(size_t)(it * 2 + 3) * 128 + c * 32 + l];
            }
        }

        // per-row multivectors: uniform broadcast loads
        float4 P0a = __ldg(Pp + (size_t)it * 4 + 0);
        float4 P0b = __ldg(Pp + (size_t)it * 4 + 1);
        float4 P1a = __ldg(Pp + (size_t)it * 4 + 2);
        float4 P1b = __ldg(Pp + (size_t)it * 4 + 3);
        float pr0[8] = {P0a.x, P0a.y, P0a.z, P0a.w, P0b.x, P0b.y, P0b.z, P0b.w};
        float pr1[8] = {P1a.x, P1a.y, P1a.z, P1a.w, P1b.x, P1b.y, P1b.z, P1b.w};

        // v = x + F + sum_i pr_i * SW2[i][:]
#pragma unroll
        for (int c = 0; c < 4; ++c) {
            float4 f4 = *(const float4*)&F_s[c * 128 + l * 4];
            v0[c].x += f4.x; v0[c].y += f4.y; v0[c].z += f4.z; v0[c].w += f4.w;
            v1[c].x += f4.x; v1[c].y += f4.y; v1[c].z += f4.z; v1[c].w += f4.w;
        }
#pragma unroll
        for (int i = 0; i < MV; ++i) {
            float a = pr0[i], bq = pr1[i];
#pragma unroll
            for (int c = 0; c < 4; ++c) {
                uint2 u = *(const uint2*)&SW2_s[i * DD + c * 128 + l * 4];
                float2 s01 = __bfloat1622float2(*(const __nv_bfloat162*)&u.x);
                float2 s23 = __bfloat1622float2(*(const __nv_bfloat162*)&u.y);
                v0[c].x += a * s01.x;  v0[c].y += a * s01.y;
                v0[c].z += a * s23.x;  v0[c].w += a * s23.y;
                v1[c].x += bq * s01.x; v1[c].y += bq * s01.y;
                v1[c].z += bq * s23.x; v1[c].w += bq * s23.y;
            }
        }

        // LayerNorm stats: group reduce + 4-way select + cross
        float s0 = 0.f, q0 = 0.f, s1 = 0.f, q1 = 0.f;
#pragma unroll
        for (int c = 0; c < 4; ++c) {
            s0 += v0[c].x + v0[c].y + v0[c].z + v0[c].w;
            q0 += v0[c].x * v0[c].x + v0[c].y * v0[c].y + v0[c].z * v0[c].z + v0[c].w * v0[c].w;
            s1 += v1[c].x + v1[c].y + v1[c].z + v1[c].w;
            q1 += v1[c].x * v1[c].x + v1[c].y * v1[c].y + v1[c].z * v1[c].z + v1[c].w * v1[c].w;
        }
#pragma unroll
        for (int o = 1; o <= 2; o <<= 1) {
            s0 += __shfl_xor_sync(0xffffffffu, s0, o);
            q0 += __shfl_xor_sync(0xffffffffu, q0, o);
            s1 += __shfl_xor_sync(0xffffffffu, s1, o);
            q1 += __shfl_xor_sync(0xffffffffu, q1, o);
        }
        int g4i = l & 3;
        float sel = s0;
        if (g4i == 1) sel = q0;
        if (g4i == 2) sel = s1;
        if (g4i == 3) sel = q1;
        sel += __shfl_xor_sync(0xffffffffu, sel, 4);
        sel += __shfl_xor_sync(0xffffffffu, sel, 8);
        sel += __shfl_xor_sync(0xffffffffu, sel, 16);
        float S0 = __shfl_sync(0xffffffffu, sel, 0);
        float Q0 = __shfl_sync(0xffffffffu, sel, 1);
        float S1 = __shfl_sync(0xffffffffu, sel, 2);
        float Q1 = __shfl_sync(0xffffffffu, sel, 3);

        float mu0 = S0 * (1.f / DD), mu1 = S1 * (1.f / DD);
        float r0 = rsqrtf(Q0 * (1.f / DD) - mu0 * mu0 + EPS_F);
        float r1 = rsqrtf(Q1 * (1.f / DD) - mu1 * mu1 + EPS_F);

#pragma unroll
        for (int c = 0; c < 4; ++c) {
            float4 g4 = *(const float4*)&gm_s[c * 128 + l * 4];
            float4 b4 = *(const float4*)&bt_s[c * 128 + l * 4];
            float4 o0, o1;
            o0.x = g4.x * (v0[c].x - mu0) * r0 + b4.x;
            o0.y = g4.y * (v0[c].y - mu0) * r0 + b4.y;
            o0.z = g4.z * (v0[c].z - mu0) * r0 + b4.z;
            o0.w = g4.w * (v0[c].w - mu0) * r0 + b4.w;
            o1.x = g4.x * (v1[c].x - mu1) * r1 + b4.x;
            o1.y = g4.y * (v1[c].y - mu1) * r1 + b4.y;
            o1.z = g4.z * (v1[c].z - mu1) * r1 + b4.z;
            o1.w = g4.w * (v1[c].w - mu1) * r1 + b4.w;
            stcs(&yp[(size_t)(it * 2) * 128 + c * 32 + l], o0);
            stcs(&yp[(size_t)(it * 2 + 1) * 128 + c * 32 + l], o1);
        }

        if (it < 7) {
#pragma unroll
            for (int c = 0; c < 4; ++c) { v0[c] = n0[c]; v1[c] = n1[c]; }
        }
    }
}

// ---------------------------------------------------------------------------
extern "C" void kernel_launch(void* const* d_in, const int* in_sizes, int n_in,
                              void* d_out, int out_size) {
    const float* x     = (const float*)d_in[0];
    const float* Wp    = (const float*)d_in[1];
    const float* bp    = (const float*)d_in[2];
    const float* Wm    = (const float*)d_in[3];
    const float* bm    = (const float*)d_in[4];
    const float* Wo    = (const float*)d_in[5];
    const float* bo    = (const float*)d_in[6];
    const float* gamma = (const float*)d_in[7];
    const float* beta  = (const float*)d_in[8];
    float* y = (float*)d_out;

    dim3 ga(NBA, BB);
    k_dots<<<ga, 256>>>(x, Wp, bp);
    k_prep<<<BB, 512>>>(Wm, bm, Wo, bo);
    dim3 gb(NBB, BB);
    k_out<<<gb, 256>>>(x, gamma, beta, y);
}

// round 10
// speedup vs baseline: 1.1415x; 1.1415x over previous
#include <cuda_runtime.h>
#include <cuda_bf16.h>

#define BB 8
#define NN 16384
#define DD 512
#define MV 8
#define SS 128                      // N-splits in pass 1
#define RPS (NN / SS)               // rows per split = 128
#define NBLK 128                    // blocks per batch in pass 3
#define SCALE_F 0.1f
#define EPS_F 1e-5f

typedef unsigned long long u64;

__device__ float g_partial[BB][SS][DD];        // 2 MB  column partial sums
__device__ float g_F[BB][DD];                  // F' = SCALE*(bo + sum_i bp_i*W2_i)
__device__ __nv_bfloat16 g_Wph[MV * DD];       // Wp in bf16
__device__ __nv_bfloat16 g_SW2h[BB][MV * DD];  // SCALE*Cayley-folded Wo, bf16

// ---- packed f32x2 helpers ---------------------------------------------------
__device__ __forceinline__ u64 f2u(float2 f) {
    u64 r; asm("mov.b64 %0, {%1, %2};" : "=l"(r) : "f"(f.x), "f"(f.y)); return r;
}
__device__ __forceinline__ u64 splat2(float x) {
    u64 r; asm("mov.b64 %0, {%1, %1};" : "=l"(r) : "f"(x)); return r;
}
__device__ __forceinline__ void fma2acc(u64& d, u64 a, u64 b) {
    asm("fma.rn.f32x2 %0, %1, %2, %0;" : "+l"(d) : "l"(a), "l"(b));
}
__device__ __forceinline__ u64 fma2(u64 a, u64 b, u64 c) {
    u64 d; asm("fma.rn.f32x2 %0, %1, %2, %3;" : "=l"(d) : "l"(a), "l"(b), "l"(c));
    return d;
}
__device__ __forceinline__ void add2acc(u64& d, u64 a) {
    asm("add.rn.f32x2 %0, %1, %0;" : "+l"(d) : "l"(a));
}
__device__ __forceinline__ float hsum2(u64 v) {
    float a, b; asm("mov.b64 {%0, %1}, %2;" : "=f"(a), "=f"(b) : "l"(v));
    return a + b;
}
__device__ __forceinline__ void stcs2(void* p, u64 a, u64 b) {
    asm volatile("st.global.cs.v2.b64 [%0], {%1, %2};" :: "l"(p), "l"(a), "l"(b));
}

// ---------------------------------------------------------------------------
// Pass 1: pure streaming column sums (proven ~44us @ 79% DRAM).
// ---------------------------------------------------------------------------
__global__ void k_partial(const float* __restrict__ x) {
    int b = blockIdx.y, s = blockIdx.x, t = threadIdx.x;  // t in [0,128)
    const float4* xp = (const float4*)(x + ((size_t)b * NN + (size_t)s * RPS) * DD);
    float4 a0 = make_float4(0.f, 0.f, 0.f, 0.f);
    float4 a1 = make_float4(0.f, 0.f, 0.f, 0.f);
#pragma unroll 4
    for (int r = 0; r < RPS; r += 2) {
        float4 v0 = xp[(size_t)r * 128 + t];
        float4 v1 = xp[(size_t)(r + 1) * 128 + t];
        a0.x += v0.x; a0.y += v0.y; a0.z += v0.z; a0.w += v0.w;
        a1.x += v1.x; a1.y += v1.y; a1.z += v1.z; a1.w += v1.w;
    }
    a0.x += a1.x; a0.y += a1.y; a0.z += a1.z; a0.w += a1.w;
    ((float4*)&g_partial[b][s][0])[t] = a0;
}

// ---------------------------------------------------------------------------
// Pass 2: per-batch prep. mean -> mf -> Cayley fold -> SW2(bf16), F', Wp(bf16)
// ---------------------------------------------------------------------------
__global__ void k_prep(const float* __restrict__ Wm, const float* __restrict__ bm,
                       const float* __restrict__ Wo, const float* __restrict__ bp,
                       const float* __restrict__ bo, const float* __restrict__ Wp) {
    __shared__ float mean_s[DD];
    __shared__ float mf_s[MV];
    __shared__ float M_s[MV][MV];
    int b = blockIdx.x, t = threadIdx.x;  // 512 threads

    float acc = 0.f;
    for (int s = 0; s < SS; ++s) acc += g_partial[b][s][t];
    mean_s[t] = acc * (1.0f / NN);

#pragma unroll
    for (int i = 0; i < MV; ++i)
        g_Wph[i * DD + t] = __float2bfloat16(Wp[i * DD + t]);
    __syncthreads();

    int w = t >> 5, l = t & 31;
    if (w < MV) {
        float p = 0.f;
#pragma unroll
        for (int c = 0; c < 16; ++c) p += mean_s[l + 32 * c] * Wm[w * DD + l + 32 * c];
#pragma unroll
        for (int o = 16; o; o >>= 1) p += __shfl_xor_sync(0xffffffffu, p, o);
        if (l == 0) mf_s[w] = p + bm[w];
    }
    __syncthreads();

    if (t < 64) {
        const int maskT[8] = {0, 1, 2, 4, 3, 5, 6, 7};
        const int idxT[8]  = {0, 1, 2, 4, 3, 5, 6, 7};
        int i = t >> 3, j = t & 7;
        int a = maskT[i], bj = maskT[j];
        int sgn = 0, aa = a >> 1;
        while (aa) { sgn += __popc(aa & bj); aa >>= 1; }
        int k = idxT[a ^ bj];
        M_s[i][k] = ((sgn & 1) ? -1.f : 1.f) * mf_s[j];
    }
    __syncthreads();

    float wo[8];
#pragma unroll
    for (int k = 0; k < 8; ++k) wo[k] = Wo[t * 8 + k];
    float fb = 0.f;
#pragma unroll
    for (int i = 0; i < MV; ++i) {
        float w2 = 0.f;
#pragma unroll
        for (int k = 0; k < 8; ++k) w2 += M_s[i][k] * wo[k];
        g_SW2h[b][i * DD + t] = __float2bfloat16(SCALE_F * w2);
        fb += bp[i] * w2;
    }
    g_F[b][t] = SCALE_F * (fb + bo[t]);
}

// ---------------------------------------------------------------------------
// Pass 3: fused dots + combine + LN, FFMA2 packed math inside R7 shell.
// grid (NBLK, BB), 256 threads (8 warps). Warp: 16 rows, 2/iter, prefetch.
// ---------------------------------------------------------------------------
__global__ void __launch_bounds__(256, 3)
k_main(const float* __restrict__ x, const float* __restrict__ gamma,
       const float* __restrict__ beta, float* __restrict__ y) {
    __shared__ __nv_bfloat16 Wp_s[MV * DD];    // 8 KB
    __shared__ __nv_bfloat16 SW2_s[MV * DD];   // 8 KB
    __shared__ float F_s[DD], gm_s[DD], bt_s[DD];
    __shared__ float prbuf[2][8][16];          // ping-pong per-warp dot results

    int b = blockIdx.y, t = threadIdx.x;
    const __nv_bfloat16* sw2g = &g_SW2h[b][0];
    for (int i = t; i < MV * DD; i += 256) { Wp_s[i] = g_Wph[i]; SW2_s[i] = sw2g[i]; }
    for (int i = t; i < DD; i += 256) { F_s[i] = g_F[b][i]; gm_s[i] = gamma[i]; bt_s[i] = beta[i]; }
    __syncthreads();

    int w = t >> 5, l = t & 31;
    int g = l & 7;
    size_t rowbase = (size_t)blockIdx.x * 128 + (size_t)w * 16;
    const ulonglong2* xp = (const ulonglong2*)(x + ((size_t)b * NN + rowbase) * DD);
    ulonglong2* yp = (ulonglong2*)(y + ((size_t)b * NN + rowbase) * DD);

    // prologue: load iteration 0 (each ulonglong2 = one float4 of x as 2 pairs)
    ulonglong2 v0[4], v1[4];
#pragma unroll
    for (int c = 0; c < 4; ++c) {
        v0[c] = xp[c * 32 + l];
        v1[c] = xp[128 + c * 32 + l];
    }

    for (int it = 0; it < 8; ++it) {
        int pp = it & 1;
        // prefetch next iteration's x
        ulonglong2 n0[4], n1[4];
        if (it < 7) {
#pragma unroll
            for (int c = 0; c < 4; ++c) {
                n0[c] = xp[(size_t)(it * 2 + 2) * 128 + c * 32 + l];
                n1[c] = xp[(size_t)(it * 2 + 3) * 128 + c * 32 + l];
            }
        }

        // 8 per-lane partial dots per row: packed FFMA2 (bf16 cvt -> f32 pairs)
        float p0[8], p1[8];
#pragma unroll
        for (int i = 0; i < MV; ++i) {
            u64 a0 = 0ULL, a1 = 0ULL;
#pragma unroll
            for (int c = 0; c < 4; ++c) {
                uint2 u = *(const uint2*)&Wp_s[i * DD + c * 128 + l * 4];
                u64 w01 = f2u(__bfloat1622float2(*(const __nv_bfloat162*)&u.x));
                u64 w23 = f2u(__bfloat1622float2(*(const __nv_bfloat162*)&u.y));
                fma2acc(a0, v0[c].x, w01); fma2acc(a0, v0[c].y, w23);
                fma2acc(a1, v1[c].x, w01); fma2acc(a1, v1[c].y, w23);
            }
            p0[i] = hsum2(a0); p1[i] = hsum2(a1);
        }
        // group reduce (1,2,4), select component g, cross-group (8,16)
#pragma unroll
        for (int o = 1; o <= 4; o <<= 1) {
#pragma unroll
            for (int i = 0; i < MV; ++i) {
                p0[i] += __shfl_xor_sync(0xffffffffu, p0[i], o);
                p1[i] += __shfl_xor_sync(0xffffffffu, p1[i], o);
            }
        }
        float vd0 = p0[0], vd1 = p1[0];
#pragma unroll
        for (int i = 1; i < MV; ++i) { if (g == i) { vd0 = p0[i]; vd1 = p1[i]; } }
        vd0 += __shfl_xor_sync(0xffffffffu, vd0, 8);
        vd0 += __shfl_xor_sync(0xffffffffu, vd0, 16);
        vd1 += __shfl_xor_sync(0xffffffffu, vd1, 8);
        vd1 += __shfl_xor_sync(0xffffffffu, vd1, 16);

        // broadcast via per-warp smem ping-pong
        if (l < 16) prbuf[pp][w][l] = (l < 8) ? vd0 : vd1;
        __syncwarp();
        float4 q0a = *(const float4*)&prbuf[pp][w][0];
        float4 q0b = *(const float4*)&prbuf[pp][w][4];
        float4 q1a = *(const float4*)&prbuf[pp][w][8];
        float4 q1b = *(const float4*)&prbuf[pp][w][12];
        float pr0[8] = {q0a.x, q0a.y, q0a.z, q0a.w, q0b.x, q0b.y, q0b.z, q0b.w};
        float pr1[8] = {q1a.x, q1a.y, q1a.z, q1a.w, q1b.x, q1b.y, q1b.z, q1b.w};

        // v = x + F' (packed)
#pragma unroll
        for (int c = 0; c < 4; ++c) {
            ulonglong2 f4 = *(const ulonglong2*)&F_s[c * 128 + l * 4];
            add2acc(v0[c].x, f4.x); add2acc(v0[c].y, f4.y);
            add2acc(v1[c].x, f4.x); add2acc(v1[c].y, f4.y);
        }
        // v += sum_i pr_i * SW2[i][:]  (packed; splat one pr at a time)
#pragma unroll
        for (int i = 0; i < MV; ++i) {
            u64 s0 = splat2(pr0[i]);
            u64 s1 = splat2(pr1[i]);
#pragma unroll
            for (int c = 0; c < 4; ++c) {
                uint2 u = *(const uint2*)&SW2_s[i * DD + c * 128 + l * 4];
                u64 w01 = f2u(__bfloat1622float2(*(const __nv_bfloat162*)&u.x));
                u64 w23 = f2u(__bfloat1622float2(*(const __nv_bfloat162*)&u.y));
                fma2acc(v0[c].x, s0, w01); fma2acc(v0[c].y, s0, w23);
                fma2acc(v1[c].x, s1, w01); fma2acc(v1[c].y, s1, w23);
            }
        }

        // LayerNorm stats (packed accumulate, then horizontal + tree)
        u64 sa = 0ULL, qa = 0ULL, sb = 0ULL, qb = 0ULL;
#pragma unroll
        for (int c = 0; c < 4; ++c) {
            add2acc(sa, v0[c].x); add2acc(sa, v0[c].y);
            fma2acc(qa, v0[c].x, v0[c].x); fma2acc(qa, v0[c].y, v0[c].y);
            add2acc(sb, v1[c].x); add2acc(sb, v1[c].y);
            fma2acc(qb, v1[c].x, v1[c].x); fma2acc(qb, v1[c].y, v1[c].y);
        }
        float s0v = hsum2(sa), q0v = hsum2(qa);
        float s1v = hsum2(sb), q1v = hsum2(qb);
#pragma unroll
        for (int o = 1; o <= 2; o <<= 1) {
            s0v += __shfl_xor_sync(0xffffffffu, s0v, o);
            q0v += __shfl_xor_sync(0xffffffffu, q0v, o);
            s1v += __shfl_xor_sync(0xffffffffu, s1v, o);
            q1v += __shfl_xor_sync(0xffffffffu, q1v, o);
        }
        int g4i = l & 3;
        float sel = s0v;
        if (g4i == 1) sel = q0v;
        if (g4i == 2) sel = s1v;
        if (g4i == 3) sel = q1v;
        sel += __shfl_xor_sync(0xffffffffu, sel, 4);
        sel += __shfl_xor_sync(0xffffffffu, sel, 8);
        sel += __shfl_xor_sync(0xffffffffu, sel, 16);
        float S0 = __shfl_sync(0xffffffffu, sel, 0);
        float Q0 = __shfl_sync(0xffffffffu, sel, 1);
        float S1 = __shfl_sync(0xffffffffu, sel, 2);
        float Q1 = __shfl_sync(0xffffffffu, sel, 3);

        float mu0 = S0 * (1.f / DD), mu1 = S1 * (1.f / DD);
        float r0 = rsqrtf(Q0 * (1.f / DD) - mu0 * mu0 + EPS_F);
        float r1 = rsqrtf(Q1 * (1.f / DD) - mu1 * mu1 + EPS_F);
        u64 rp0 = splat2(r0), mr0 = splat2(-mu0 * r0);
        u64 rp1 = splat2(r1), mr1 = splat2(-mu1 * r1);

        // normalize + store (packed; v2.b64 streaming stores)
#pragma unroll
        for (int c = 0; c < 4; ++c) {
            ulonglong2 g4 = *(const ulonglong2*)&gm_s[c * 128 + l * 4];
            ulonglong2 b4 = *(const ulonglong2*)&bt_s[c * 128 + l * 4];
            u64 o0x = fma2(g4.x, fma2(v0[c].x, rp0, mr0), b4.x);
            u64 o0y = fma2(g4.y, fma2(v0[c].y, rp0, mr0), b4.y);
            u64 o1x = fma2(g4.x, fma2(v1[c].x, rp1, mr1), b4.x);
            u64 o1y = fma2(g4.y, fma2(v1[c].y, rp1, mr1), b4.y);
            stcs2(&yp[(size_t)(it * 2) * 128 + c * 32 + l], o0x, o0y);
            stcs2(&yp[(size_t)(it * 2 + 1) * 128 + c * 32 + l], o1x, o1y);
        }

        // rotate prefetch buffers
        if (it < 7) {
#pragma unroll
            for (int c = 0; c < 4; ++c) { v0[c] = n0[c]; v1[c] = n1[c]; }
        }
    }
}

// ---------------------------------------------------------------------------
extern "C" void kernel_launch(void* const* d_in, const int* in_sizes, int n_in,
                              void* d_out, int out_size) {
    const float* x     = (const float*)d_in[0];
    const float* Wp    = (const float*)d_in[1];
    const float* bp    = (const float*)d_in[2];
    const float* Wm    = (const float*)d_in[3];
    const float* bm    = (const float*)d_in[4];
    const float* Wo    = (const float*)d_in[5];
    const float* bo    = (const float*)d_in[6];
    const float* gamma = (const float*)d_in[7];
    const float* beta  = (const float*)d_in[8];
    float* y = (float*)d_out;

    dim3 g1(SS, BB);
    k_partial<<<g1, 128>>>(x);
    k_prep<<<BB, 512>>>(Wm, bm, Wo, bp, bo, Wp);
    dim3 g3(NBLK, BB);
    k_main<<<g3, 256>>>(x, gamma, beta, y);
}

// round 11
// speedup vs baseline: 1.3910x; 1.2186x over previous
#include <cuda_runtime.h>
#include <cuda_bf16.h>

#define BB 8
#define NN 16384
#define DD 512
#define MV 8
#define SS 128                      // N-splits in pass 1
#define RPS (NN / SS)               // rows per split = 128
#define NBLK 128                    // blocks per batch in pass 3
#define SCALE_F 0.1f
#define EPS_F 1e-5f

__device__ float g_partial[BB][SS][DD];        // 2 MB  column partial sums
__device__ float g_F[BB][DD];                  // F' = SCALE*(bo + sum_i bp_i*W2_i)
__device__ __nv_bfloat16 g_Wph[MV * DD];       // Wp in bf16
__device__ __nv_bfloat16 g_SW2h[BB][MV * DD];  // SCALE*Cayley-folded Wo, bf16

__device__ __forceinline__ void stcs(float4* p, float4 v) {
    asm volatile("st.global.cs.v4.f32 [%0], {%1,%2,%3,%4};"
                 :: "l"(p), "f"(v.x), "f"(v.y), "f"(v.z), "f"(v.w));
}

// ---------------------------------------------------------------------------
// Pass 1: pure streaming column sums (proven ~44us @ 79% DRAM).
// ---------------------------------------------------------------------------
__global__ void k_partial(const float* __restrict__ x) {
    int b = blockIdx.y, s = blockIdx.x, t = threadIdx.x;  // t in [0,128)
    const float4* xp = (const float4*)(x + ((size_t)b * NN + (size_t)s * RPS) * DD);
    float4 a0 = make_float4(0.f, 0.f, 0.f, 0.f);
    float4 a1 = make_float4(0.f, 0.f, 0.f, 0.f);
#pragma unroll 4
    for (int r = 0; r < RPS; r += 2) {
        float4 v0 = xp[(size_t)r * 128 + t];
        float4 v1 = xp[(size_t)(r + 1) * 128 + t];
        a0.x += v0.x; a0.y += v0.y; a0.z += v0.z; a0.w += v0.w;
        a1.x += v1.x; a1.y += v1.y; a1.z += v1.z; a1.w += v1.w;
    }
    a0.x += a1.x; a0.y += a1.y; a0.z += a1.z; a0.w += a1.w;
    ((float4*)&g_partial[b][s][0])[t] = a0;
}

// ---------------------------------------------------------------------------
// Pass 2: per-batch prep. mean -> mf -> Cayley fold -> SW2(bf16), F', Wp(bf16)
// ---------------------------------------------------------------------------
__global__ void k_prep(const float* __restrict__ Wm, const float* __restrict__ bm,
                       const float* __restrict__ Wo, const float* __restrict__ bp,
                       const float* __restrict__ bo, const float* __restrict__ Wp) {
    __shared__ float mean_s[DD];
    __shared__ float mf_s[MV];
    __shared__ float M_s[MV][MV];
    int b = blockIdx.x, t = threadIdx.x;  // 512 threads

    float acc = 0.f;
    for (int s = 0; s < SS; ++s) acc += g_partial[b][s][t];
    mean_s[t] = acc * (1.0f / NN);

#pragma unroll
    for (int i = 0; i < MV; ++i)
        g_Wph[i * DD + t] = __float2bfloat16(Wp[i * DD + t]);
    __syncthreads();

    int w = t >> 5, l = t & 31;
    if (w < MV) {
        float p = 0.f;
#pragma unroll
        for (int c = 0; c < 16; ++c) p += mean_s[l + 32 * c] * Wm[w * DD + l + 32 * c];
#pragma unroll
        for (int o = 16; o; o >>= 1) p += __shfl_xor_sync(0xffffffffu, p, o);
        if (l == 0) mf_s[w] = p + bm[w];
    }
    __syncthreads();

    if (t < 64) {
        const int maskT[8] = {0, 1, 2, 4, 3, 5, 6, 7};
        const int idxT[8]  = {0, 1, 2, 4, 3, 5, 6, 7};
        int i = t >> 3, j = t & 7;
        int a = maskT[i], bj = maskT[j];
        int sgn = 0, aa = a >> 1;
        while (aa) { sgn += __popc(aa & bj); aa >>= 1; }
        int k = idxT[a ^ bj];
        M_s[i][k] = ((sgn & 1) ? -1.f : 1.f) * mf_s[j];
    }
    __syncthreads();

    float wo[8];
#pragma unroll
    for (int k = 0; k < 8; ++k) wo[k] = Wo[t * 8 + k];
    float fb = 0.f;
#pragma unroll
    for (int i = 0; i < MV; ++i) {
        float w2 = 0.f;
#pragma unroll
        for (int k = 0; k < 8; ++k) w2 += M_s[i][k] * wo[k];
        g_SW2h[b][i * DD + t] = __float2bfloat16(SCALE_F * w2);
        fb += bp[i] * w2;
    }
    g_F[b][t] = SCALE_F * (fb + bo[t]);
}

// ---------------------------------------------------------------------------
// Pass 3: fused dots + combine + LN. grid (NBLK, BB), 256 threads (8 warps),
// occ 4 (32 warps/SM). Warp: 16 rows, 2/iter. No prefetch buffers, no pr
// register arrays — latency hidden by warp count.
// ---------------------------------------------------------------------------
__global__ void __launch_bounds__(256, 4)
k_main(const float* __restrict__ x, const float* __restrict__ gamma,
       const float* __restrict__ beta, float* __restrict__ y) {
    __shared__ __nv_bfloat16 Wp_s[MV * DD];    // 8 KB
    __shared__ __nv_bfloat16 SW2_s[MV * DD];   // 8 KB
    __shared__ float F_s[DD], gm_s[DD], bt_s[DD];
    __shared__ float prbuf[2][8][16];          // ping-pong per-warp dot results

    int b = blockIdx.y, t = threadIdx.x;
    const __nv_bfloat16* sw2g = &g_SW2h[b][0];
    for (int i = t; i < MV * DD; i += 256) { Wp_s[i] = g_Wph[i]; SW2_s[i] = sw2g[i]; }
    for (int i = t; i < DD; i += 256) { F_s[i] = g_F[b][i]; gm_s[i] = gamma[i]; bt_s[i] = beta[i]; }
    __syncthreads();

    int w = t >> 5, l = t & 31;
    int g = l & 7;
    size_t rowbase = (size_t)blockIdx.x * 128 + (size_t)w * 16;
    const float4* xp = (const float4*)(x + ((size_t)b * NN + rowbase) * DD);
    float4* yp = (float4*)(y + ((size_t)b * NN + rowbase) * DD);

    for (int it = 0; it < 8; ++it) {
        int pp = it & 1;
        float4 v0[4], v1[4];
#pragma unroll
        for (int c = 0; c < 4; ++c) {
            v0[c] = xp[(size_t)(it * 2) * 128 + c * 32 + l];
            v1[c] = xp[(size_t)(it * 2 + 1) * 128 + c * 32 + l];
        }

        // 8 per-lane partial dots per row (bf16 weights)
        float p0[8], p1[8];
#pragma unroll
        for (int i = 0; i < MV; ++i) {
            float s0 = 0.f, s1 = 0.f;
#pragma unroll
            for (int c = 0; c < 4; ++c) {
                uint2 u = *(const uint2*)&Wp_s[i * DD + c * 128 + l * 4];
                float2 a01 = __bfloat1622float2(*(const __nv_bfloat162*)&u.x);
                float2 a23 = __bfloat1622float2(*(const __nv_bfloat162*)&u.y);
                s0 += v0[c].x * a01.x + v0[c].y * a01.y + v0[c].z * a23.x + v0[c].w * a23.y;
                s1 += v1[c].x * a01.x + v1[c].y * a01.y + v1[c].z * a23.x + v1[c].w * a23.y;
            }
            p0[i] = s0; p1[i] = s1;
        }
        // group reduce (1,2,4), select component g, cross-group (8,16)
#pragma unroll
        for (int o = 1; o <= 4; o <<= 1) {
#pragma unroll
            for (int i = 0; i < MV; ++i) {
                p0[i] += __shfl_xor_sync(0xffffffffu, p0[i], o);
                p1[i] += __shfl_xor_sync(0xffffffffu, p1[i], o);
            }
        }
        float vd0 = p0[0], vd1 = p1[0];
#pragma unroll
        for (int i = 1; i < MV; ++i) { if (g == i) { vd0 = p0[i]; vd1 = p1[i]; } }
        vd0 += __shfl_xor_sync(0xffffffffu, vd0, 8);
        vd0 += __shfl_xor_sync(0xffffffffu, vd0, 16);
        vd1 += __shfl_xor_sync(0xffffffffu, vd1, 8);
        vd1 += __shfl_xor_sync(0xffffffffu, vd1, 16);

        // stash dot results in per-warp smem (ping-pong)
        if (l < 16) prbuf[pp][w][l] = (l < 8) ? vd0 : vd1;
        __syncwarp();

        // v = x + F'
#pragma unroll
        for (int c = 0; c < 4; ++c) {
            float4 f4 = *(const float4*)&F_s[c * 128 + l * 4];
            v0[c].x += f4.x; v0[c].y += f4.y; v0[c].z += f4.z; v0[c].w += f4.w;
            v1[c].x += f4.x; v1[c].y += f4.y; v1[c].z += f4.z; v1[c].w += f4.w;
        }
        // v += P_i * SW2[i][:], P_i read by broadcast LDS at point of use
#pragma unroll
        for (int i = 0; i < MV; ++i) {
            float a = prbuf[pp][w][i];
            float bq = prbuf[pp][w][8 + i];
#pragma unroll
            for (int c = 0; c < 4; ++c) {
                uint2 u = *(const uint2*)&SW2_s[i * DD + c * 128 + l * 4];
                float2 s01 = __bfloat1622float2(*(const __nv_bfloat162*)&u.x);
                float2 s23 = __bfloat1622float2(*(const __nv_bfloat162*)&u.y);
                v0[c].x += a * s01.x;  v0[c].y += a * s01.y;
                v0[c].z += a * s23.x;  v0[c].w += a * s23.y;
                v1[c].x += bq * s01.x; v1[c].y += bq * s01.y;
                v1[c].z += bq * s23.x; v1[c].w += bq * s23.y;
            }
        }

        // LayerNorm stats: group reduce + 4-way select + cross
        float s0 = 0.f, q0 = 0.f, s1 = 0.f, q1 = 0.f;
#pragma unroll
        for (int c = 0; c < 4; ++c) {
            s0 += v0[c].x + v0[c].y + v0[c].z + v0[c].w;
            q0 += v0[c].x * v0[c].x + v0[c].y * v0[c].y + v0[c].z * v0[c].z + v0[c].w * v0[c].w;
            s1 += v1[c].x + v1[c].y + v1[c].z + v1[c].w;
            q1 += v1[c].x * v1[c].x + v1[c].y * v1[c].y + v1[c].z * v1[c].z + v1[c].w * v1[c].w;
        }
#pragma unroll
        for (int o = 1; o <= 2; o <<= 1) {
            s0 += __shfl_xor_sync(0xffffffffu, s0, o);
            q0 += __shfl_xor_sync(0xffffffffu, q0, o);
            s1 += __shfl_xor_sync(0xffffffffu, s1, o);
            q1 += __shfl_xor_sync(0xffffffffu, q1, o);
        }
        int g4i = l & 3;
        float sel = s0;
        if (g4i == 1) sel = q0;
        if (g4i == 2) sel = s1;
        if (g4i == 3) sel = q1;
        sel += __shfl_xor_sync(0xffffffffu, sel, 4);
        sel += __shfl_xor_sync(0xffffffffu, sel, 8);
        sel += __shfl_xor_sync(0xffffffffu, sel, 16);
        float S0 = __shfl_sync(0xffffffffu, sel, 0);
        float Q0 = __shfl_sync(0xffffffffu, sel, 1);
        float S1 = __shfl_sync(0xffffffffu, sel, 2);
        float Q1 = __shfl_sync(0xffffffffu, sel, 3);

        float mu0 = S0 * (1.f / DD), mu1 = S1 * (1.f / DD);
        float r0 = rsqrtf(Q0 * (1.f / DD) - mu0 * mu0 + EPS_F);
        float r1 = rsqrtf(Q1 * (1.f / DD) - mu1 * mu1 + EPS_F);

#pragma unroll
        for (int c = 0; c < 4; ++c) {
            float4 g4 = *(const float4*)&gm_s[c * 128 + l * 4];
            float4 b4 = *(const float4*)&bt_s[c * 128 + l * 4];
            float4 o0, o1;
            o0.x = g4.x * (v0[c].x - mu0) * r0 + b4.x;
            o0.y = g4.y * (v0[c].y - mu0) * r0 + b4.y;
            o0.z = g4.z * (v0[c].z - mu0) * r0 + b4.z;
            o0.w = g4.w * (v0[c].w - mu0) * r0 + b4.w;
            o1.x = g4.x * (v1[c].x - mu1) * r1 + b4.x;
            o1.y = g4.y * (v1[c].y - mu1) * r1 + b4.y;
            o1.z = g4.z * (v1[c].z - mu1) * r1 + b4.z;
            o1.w = g4.w * (v1[c].w - mu1) * r1 + b4.w;
            stcs(&yp[(size_t)(it * 2) * 128 + c * 32 + l], o0);
            stcs(&yp[(size_t)(it * 2 + 1) * 128 + c * 32 + l], o1);
        }
    }
}

// ---------------------------------------------------------------------------
extern "C" void kernel_launch(void* const* d_in, const int* in_sizes, int n_in,
                              void* d_out, int out_size) {
    const float* x     = (const float*)d_in[0];
    const float* Wp    = (const float*)d_in[1];
    const float* bp    = (const float*)d_in[2];
    const float* Wm    = (const float*)d_in[3];
    const float* bm    = (const float*)d_in[4];
    const float* Wo    = (const float*)d_in[5];
    const float* bo    = (const float*)d_in[6];
    const float* gamma = (const float*)d_in[7];
    const float* beta  = (const float*)d_in[8];
    float* y = (float*)d_out;

    dim3 g1(SS, BB);
    k_partial<<<g1, 128>>>(x);
    k_prep<<<BB, 512>>>(Wm, bm, Wo, bp, bo, Wp);
    dim3 g3(NBLK, BB);
    k_main<<<g3, 256>>>(x, gamma, beta, y);
}

// round 12
// speedup vs baseline: 1.4319x; 1.0294x over previous
#include <cuda_runtime.h>
#include <cuda_bf16.h>

#define BB 8
#define NN 16384
#define DD 512
#define MV 8
#define SS 128                      // N-splits in pass 1
#define RPS (NN / SS)               // rows per split = 128
#define NBLK 128                    // blocks per batch in pass 3
#define SCALE_F 0.1f
#define EPS_F 1e-5f

__device__ float g_partial[BB][SS][DD];        // 2 MB  column partial sums
__device__ float g_F[BB][DD];                  // F' = SCALE*(bo + sum_i bp_i*W2_i)
__device__ __nv_bfloat16 g_Wph[MV * DD];       // Wp in bf16
__device__ __nv_bfloat16 g_SW2h[BB][MV * DD];  // SCALE*Cayley-folded Wo, bf16

__device__ __forceinline__ void stcs(float4* p, float4 v) {
    asm volatile("st.global.cs.v4.f32 [%0], {%1,%2,%3,%4};"
                 :: "l"(p), "f"(v.x), "f"(v.y), "f"(v.z), "f"(v.w));
}
// splat float -> bf16x2 {lo=x, hi=x}
__device__ __forceinline__ unsigned splatbf2(float x) {
    unsigned r;
    asm("cvt.rn.bf16x2.f32 %0, %1, %2;" : "=r"(r) : "f"(x), "f"(x));
    return r;
}
__device__ __forceinline__ void hfma2acc(unsigned& d, unsigned a, unsigned b) {
    asm("fma.rn.bf16x2 %0, %1, %2, %0;" : "+r"(d) : "r"(a), "r"(b));
}

// ---------------------------------------------------------------------------
// Pass 1: pure streaming column sums (proven ~44us @ 79% DRAM).
// ---------------------------------------------------------------------------
__global__ void k_partial(const float* __restrict__ x) {
    int b = blockIdx.y, s = blockIdx.x, t = threadIdx.x;  // t in [0,128)
    const float4* xp = (const float4*)(x + ((size_t)b * NN + (size_t)s * RPS) * DD);
    float4 a0 = make_float4(0.f, 0.f, 0.f, 0.f);
    float4 a1 = make_float4(0.f, 0.f, 0.f, 0.f);
#pragma unroll 4
    for (int r = 0; r < RPS; r += 2) {
        float4 v0 = xp[(size_t)r * 128 + t];
        float4 v1 = xp[(size_t)(r + 1) * 128 + t];
        a0.x += v0.x; a0.y += v0.y; a0.z += v0.z; a0.w += v0.w;
        a1.x += v1.x; a1.y += v1.y; a1.z += v1.z; a1.w += v1.w;
    }
    a0.x += a1.x; a0.y += a1.y; a0.z += a1.z; a0.w += a1.w;
    ((float4*)&g_partial[b][s][0])[t] = a0;
}

// ---------------------------------------------------------------------------
// Pass 2: per-batch prep. mean -> mf -> Cayley fold -> SW2(bf16), F', Wp(bf16)
// ---------------------------------------------------------------------------
__global__ void k_prep(const float* __restrict__ Wm, const float* __restrict__ bm,
                       const float* __restrict__ Wo, const float* __restrict__ bp,
                       const float* __restrict__ bo, const float* __restrict__ Wp) {
    __shared__ float mean_s[DD];
    __shared__ float mf_s[MV];
    __shared__ float M_s[MV][MV];
    int b = blockIdx.x, t = threadIdx.x;  // 512 threads

    float acc = 0.f;
    for (int s = 0; s < SS; ++s) acc += g_partial[b][s][t];
    mean_s[t] = acc * (1.0f / NN);

#pragma unroll
    for (int i = 0; i < MV; ++i)
        g_Wph[i * DD + t] = __float2bfloat16(Wp[i * DD + t]);
    __syncthreads();

    int w = t >> 5, l = t & 31;
    if (w < MV) {
        float p = 0.f;
#pragma unroll
        for (int c = 0; c < 16; ++c) p += mean_s[l + 32 * c] * Wm[w * DD + l + 32 * c];
#pragma unroll
        for (int o = 16; o; o >>= 1) p += __shfl_xor_sync(0xffffffffu, p, o);
        if (l == 0) mf_s[w] = p + bm[w];
    }
    __syncthreads();

    if (t < 64) {
        const int maskT[8] = {0, 1, 2, 4, 3, 5, 6, 7};
        const int idxT[8]  = {0, 1, 2, 4, 3, 5, 6, 7};
        int i = t >> 3, j = t & 7;
        int a = maskT[i], bj = maskT[j];
        int sgn = 0, aa = a >> 1;
        while (aa) { sgn += __popc(aa & bj); aa >>= 1; }
        int k = idxT[a ^ bj];
        M_s[i][k] = ((sgn & 1) ? -1.f : 1.f) * mf_s[j];
    }
    __syncthreads();

    float wo[8];
#pragma unroll
    for (int k = 0; k < 8; ++k) wo[k] = Wo[t * 8 + k];
    float fb = 0.f;
#pragma unroll
    for (int i = 0; i < MV; ++i) {
        float w2 = 0.f;
#pragma unroll
        for (int k = 0; k < 8; ++k) w2 += M_s[i][k] * wo[k];
        g_SW2h[b][i * DD + t] = __float2bfloat16(SCALE_F * w2);
        fb += bp[i] * w2;
    }
    g_F[b][t] = SCALE_F * (fb + bo[t]);
}

// ---------------------------------------------------------------------------
// Pass 3: fused dots + combine + LN. grid (NBLK, BB), 256 threads (8 warps),
// occ 4 (32 warps/SM). Warp: 16 rows, 2/iter. Outer product in packed HFMA2.
// ---------------------------------------------------------------------------
__global__ void __launch_bounds__(256, 4)
k_main(const float* __restrict__ x, const float* __restrict__ gamma,
       const float* __restrict__ beta, float* __restrict__ y) {
    __shared__ __nv_bfloat16 Wp_s[MV * DD];    // 8 KB
    __shared__ __nv_bfloat16 SW2_s[MV * DD];   // 8 KB
    __shared__ float F_s[DD], gm_s[DD], bt_s[DD];
    __shared__ float prbuf[2][8][16];          // ping-pong per-warp dot results

    int b = blockIdx.y, t = threadIdx.x;
    const __nv_bfloat16* sw2g = &g_SW2h[b][0];
    for (int i = t; i < MV * DD; i += 256) { Wp_s[i] = g_Wph[i]; SW2_s[i] = sw2g[i]; }
    for (int i = t; i < DD; i += 256) { F_s[i] = g_F[b][i]; gm_s[i] = gamma[i]; bt_s[i] = beta[i]; }
    __syncthreads();

    int w = t >> 5, l = t & 31;
    int g = l & 7;
    size_t rowbase = (size_t)blockIdx.x * 128 + (size_t)w * 16;
    const float4* xp = (const float4*)(x + ((size_t)b * NN + rowbase) * DD);
    float4* yp = (float4*)(y + ((size_t)b * NN + rowbase) * DD);

    for (int it = 0; it < 8; ++it) {
        int pp = it & 1;
        float4 v0[4], v1[4];
#pragma unroll
        for (int c = 0; c < 4; ++c) {
            v0[c] = xp[(size_t)(it * 2) * 128 + c * 32 + l];
            v1[c] = xp[(size_t)(it * 2 + 1) * 128 + c * 32 + l];
        }

        // 8 per-lane partial dots per row (bf16 weights, fp32 FFMA)
        float p0[8], p1[8];
#pragma unroll
        for (int i = 0; i < MV; ++i) {
            float s0 = 0.f, s1 = 0.f;
#pragma unroll
            for (int c = 0; c < 4; ++c) {
                uint2 u = *(const uint2*)&Wp_s[i * DD + c * 128 + l * 4];
                float2 a01 = __bfloat1622float2(*(const __nv_bfloat162*)&u.x);
                float2 a23 = __bfloat1622float2(*(const __nv_bfloat162*)&u.y);
                s0 += v0[c].x * a01.x + v0[c].y * a01.y + v0[c].z * a23.x + v0[c].w * a23.y;
                s1 += v1[c].x * a01.x + v1[c].y * a01.y + v1[c].z * a23.x + v1[c].w * a23.y;
            }
            p0[i] = s0; p1[i] = s1;
        }
        // group reduce (1,2,4), select component g, cross-group (8,16)
#pragma unroll
        for (int o = 1; o <= 4; o <<= 1) {
#pragma unroll
            for (int i = 0; i < MV; ++i) {
                p0[i] += __shfl_xor_sync(0xffffffffu, p0[i], o);
                p1[i] += __shfl_xor_sync(0xffffffffu, p1[i], o);
            }
        }
        float vd0 = p0[0], vd1 = p1[0];
#pragma unroll
        for (int i = 1; i < MV; ++i) { if (g == i) { vd0 = p0[i]; vd1 = p1[i]; } }
        vd0 += __shfl_xor_sync(0xffffffffu, vd0, 8);
        vd0 += __shfl_xor_sync(0xffffffffu, vd0, 16);
        vd1 += __shfl_xor_sync(0xffffffffu, vd1, 8);
        vd1 += __shfl_xor_sync(0xffffffffu, vd1, 16);

        // stash dot results in per-warp smem (ping-pong)
        if (l < 16) prbuf[pp][w][l] = (l < 8) ? vd0 : vd1;
        __syncwarp();

        // outer product in packed bf16x2 HFMA2 (native u32 regs)
        unsigned acc0[8], acc1[8];
#pragma unroll
        for (int k2 = 0; k2 < 8; ++k2) { acc0[k2] = 0u; acc1[k2] = 0u; }
#pragma unroll
        for (int i = 0; i < MV; ++i) {
            unsigned a2 = splatbf2(prbuf[pp][w][i]);
            unsigned b2 = splatbf2(prbuf[pp][w][8 + i]);
#pragma unroll
            for (int c = 0; c < 4; ++c) {
                uint2 u = *(const uint2*)&SW2_s[i * DD + c * 128 + l * 4];
                hfma2acc(acc0[c * 2],     a2, u.x);
                hfma2acc(acc0[c * 2 + 1], a2, u.y);
                hfma2acc(acc1[c * 2],     b2, u.x);
                hfma2acc(acc1[c * 2 + 1], b2, u.y);
            }
        }
        // v = x + F' + unpacked outer contribution
#pragma unroll
        for (int c = 0; c < 4; ++c) {
            float4 f4 = *(const float4*)&F_s[c * 128 + l * 4];
            float2 e0 = __bfloat1622float2(*(const __nv_bfloat162*)&acc0[c * 2]);
            float2 e1 = __bfloat1622float2(*(const __nv_bfloat162*)&acc0[c * 2 + 1]);
            float2 e2 = __bfloat1622float2(*(const __nv_bfloat162*)&acc1[c * 2]);
            float2 e3 = __bfloat1622float2(*(const __nv_bfloat162*)&acc1[c * 2 + 1]);
            v0[c].x += f4.x + e0.x; v0[c].y += f4.y + e0.y;
            v0[c].z += f4.z + e1.x; v0[c].w += f4.w + e1.y;
            v1[c].x += f4.x + e2.x; v1[c].y += f4.y + e2.y;
            v1[c].z += f4.z + e3.x; v1[c].w += f4.w + e3.y;
        }

        // LayerNorm stats: group reduce + 4-way select + cross
        float s0 = 0.f, q0 = 0.f, s1 = 0.f, q1 = 0.f;
#pragma unroll
        for (int c = 0; c < 4; ++c) {
            s0 += v0[c].x + v0[c].y + v0[c].z + v0[c].w;
            q0 += v0[c].x * v0[c].x + v0[c].y * v0[c].y + v0[c].z * v0[c].z + v0[c].w * v0[c].w;
            s1 += v1[c].x + v1[c].y + v1[c].z + v1[c].w;
            q1 += v1[c].x * v1[c].x + v1[c].y * v1[c].y + v1[c].z * v1[c].z + v1[c].w * v1[c].w;
        }
#pragma unroll
        for (int o = 1; o <= 2; o <<= 1) {
            s0 += __shfl_xor_sync(0xffffffffu, s0, o);
            q0 += __shfl_xor_sync(0xffffffffu, q0, o);
            s1 += __shfl_xor_sync(0xffffffffu, s1, o);
            q1 += __shfl_xor_sync(0xffffffffu, q1, o);
        }
        int g4i = l & 3;
        float sel = s0;
        if (g4i == 1) sel = q0;
        if (g4i == 2) sel = s1;
        if (g4i == 3) sel = q1;
        sel += __shfl_xor_sync(0xffffffffu, sel, 4);
        sel += __shfl_xor_sync(0xffffffffu, sel, 8);
        sel += __shfl_xor_sync(0xffffffffu, sel, 16);
        float S0 = __shfl_sync(0xffffffffu, sel, 0);
        float Q0 = __shfl_sync(0xffffffffu, sel, 1);
        float S1 = __shfl_sync(0xffffffffu, sel, 2);
        float Q1 = __shfl_sync(0xffffffffu, sel, 3);

        float mu0 = S0 * (1.f / DD), mu1 = S1 * (1.f / DD);
        float r0 = rsqrtf(Q0 * (1.f / DD) - mu0 * mu0 + EPS_F);
        float r1 = rsqrtf(Q1 * (1.f / DD) - mu1 * mu1 + EPS_F);

#pragma unroll
        for (int c = 0; c < 4; ++c) {
            float4 g4 = *(const float4*)&gm_s[c * 128 + l * 4];
            float4 b4 = *(const float4*)&bt_s[c * 128 + l * 4];
            float4 o0, o1;
            o0.x = g4.x * (v0[c].x - mu0) * r0 + b4.x;
            o0.y = g4.y * (v0[c].y - mu0) * r0 + b4.y;
            o0.z = g4.z * (v0[c].z - mu0) * r0 + b4.z;
            o0.w = g4.w * (v0[c].w - mu0) * r0 + b4.w;
            o1.x = g4.x * (v1[c].x - mu1) * r1 + b4.x;
            o1.y = g4.y * (v1[c].y - mu1) * r1 + b4.y;
            o1.z = g4.z * (v1[c].z - mu1) * r1 + b4.z;
            o1.w = g4.w * (v1[c].w - mu1) * r1 + b4.w;
            stcs(&yp[(size_t)(it * 2) * 128 + c * 32 + l], o0);
            stcs(&yp[(size_t)(it * 2 + 1) * 128 + c * 32 + l], o1);
        }
    }
}

// ---------------------------------------------------------------------------
extern "C" void kernel_launch(void* const* d_in, const int* in_sizes, int n_in,
                              void* d_out, int out_size) {
    const float* x     = (const float*)d_in[0];
    const float* Wp    = (const float*)d_in[1];
    const float* bp    = (const float*)d_in[2];
    const float* Wm    = (const float*)d_in[3];
    const float* bm    = (const float*)d_in[4];
    const float* Wo    = (const float*)d_in[5];
    const float* bo    = (const float*)d_in[6];
    const float* gamma = (const float*)d_in[7];
    const float* beta  = (const float*)d_in[8];
    float* y = (float*)d_out;

    dim3 g1(SS, BB);
    k_partial<<<g1, 128>>>(x);
    k_prep<<<BB, 512>>>(Wm, bm, Wo, bp, bo, Wp);
    dim3 g3(NBLK, BB);
    k_main<<<g3, 256>>>(x, gamma, beta, y);
}